// round 1
// baseline (speedup 1.0000x reference)
#include <cuda_runtime.h>
#include <cuda_bf16.h>

#define FULL_MASK 0xFFFFFFFFu

static __device__ __forceinline__ float fast_sqrt(float x) {
    float y;
    asm("sqrt.approx.f32 %0, %1;" : "=f"(y) : "f"(x));
    return y;
}

// One block per row (B=256). 1024 threads = 32 warps.
// Row length N = 131072 outputs. Warp span = 4096, lane span = 128 (4 elems x 32 iters).
// flips bits are kept bit-packed in registers so flips is read from HBM exactly once.
__global__ __launch_bounds__(1024, 1)
void SignStickyPhaseReconstructor_kernel(const float* __restrict__ edc,
                                         const int*   __restrict__ flips,
                                         float*       __restrict__ out)
{
    const int N    = 131072;   // outputs per row (T-1)
    const int TROW = 131073;   // edc elements per row

    const int row  = blockIdx.x;
    const int lane = threadIdx.x & 31;
    const int w    = threadIdx.x >> 5;
    const unsigned lmask = (1u << lane) - 1u;

    const int4*  flips4 = (const int4*)(flips + (long long)row * N);
    const float* erow   = edc + (long long)row * TROW;
    float4*      out4   = (float4*)(out + (long long)row * N);

    const int warpBase = w * 4096;

    // ---------------- Pass 1: read flips once, build parity structure ----------------
    unsigned bitsStore[4] = {0u, 0u, 0u, 0u};  // 128 flip bits per lane
    unsigned pfx = 0u;   // bit i = parity of all flips before this lane's group at iter i (within warp)
    unsigned run = 0u;   // running warp parity across iterations

    #pragma unroll
    for (int i = 0; i < 32; i++) {
        const int t = warpBase + i * 128 + lane * 4;       // row-relative output index
        int4 fv = flips4[t >> 2];
        unsigned b0 = (unsigned)fv.x & 1u;
        unsigned b1 = (unsigned)fv.y & 1u;
        unsigned b2 = (unsigned)fv.z & 1u;
        unsigned b3 = (unsigned)fv.w & 1u;
        if (t == 0) b0 = 0u;                               // flips[:,0] is never applied
        unsigned g  = b0 | (b1 << 1) | (b2 << 2) | (b3 << 3);
        unsigned gp = b0 ^ b1 ^ b2 ^ b3;

        unsigned bal      = __ballot_sync(FULL_MASK, gp);
        unsigned laneExcl = (unsigned)__popc(bal & lmask) & 1u;
        pfx |= ((run ^ laneExcl) & 1u) << i;
        run ^= (unsigned)__popc(bal) & 1u;

        bitsStore[i >> 3] |= g << ((i & 7) * 4);
    }

    // ---------------- Block combine: XOR-scan of 32 warp parities ----------------
    __shared__ unsigned warpPar[32];
    __shared__ unsigned warpExcl[32];
    if (lane == 0) warpPar[w] = run;
    __syncthreads();
    if (w == 0) {
        unsigned p   = warpPar[lane];
        unsigned bal = __ballot_sync(FULL_MASK, p);
        warpExcl[lane] = (unsigned)__popc(bal & lmask) & 1u;
    }
    __syncthreads();
    const unsigned base = warpExcl[w];

    // ---------------- Pass 2: stream edc, emit signed sqrt(diff) ----------------
    #pragma unroll
    for (int i = 0; i < 32; i++) {
        const int t = warpBase + i * 128 + lane * 4;

        unsigned g = (bitsStore[i >> 3] >> ((i & 7) * 4)) & 0xFu;
        unsigned incl = g;
        incl ^= incl << 1;
        incl ^= incl << 2;
        incl &= 0xFu;                                      // inclusive prefix-XOR per bit
        unsigned flipAll = ((base ^ ((pfx >> i) & 1u)) & 1u) ? 0xFu : 0u;
        unsigned s = incl ^ flipAll;                       // bit k set -> negative sign

        float e0 = erow[t];
        float e1 = erow[t + 1];
        float e2 = erow[t + 2];
        float e3 = erow[t + 3];
        float e4 = __shfl_down_sync(FULL_MASK, e0, 1);     // lane l+1's e0 == erow[t+4]
        if (lane == 31) e4 = erow[t + 4];                  // warp-span boundary (in range: <= N)

        float a0 = fast_sqrt(fmaxf(e0 - e1, 0.0f));
        float a1 = fast_sqrt(fmaxf(e1 - e2, 0.0f));
        float a2 = fast_sqrt(fmaxf(e2 - e3, 0.0f));
        float a3 = fast_sqrt(fmaxf(e3 - e4, 0.0f));

        float4 o;
        o.x = (s & 1u) ? -a0 : a0;
        o.y = (s & 2u) ? -a1 : a1;
        o.z = (s & 4u) ? -a2 : a2;
        o.w = (s & 8u) ? -a3 : a3;
        out4[t >> 2] = o;
    }
}

extern "C" void kernel_launch(void* const* d_in, const int* in_sizes, int n_in,
                              void* d_out, int out_size)
{
    const int B = 256, T = 131073, N = T - 1;

    // metadata order: edc [B,T] f32, flips [B,T-1] i32. Auto-detect by element count
    // (33,554,688 vs 33,554,432) to be robust to ordering.
    const float* edc;
    const int*   flips;
    if (in_sizes[0] == B * T) {
        edc   = (const float*)d_in[0];
        flips = (const int*)  d_in[1];
    } else {
        edc   = (const float*)d_in[1];
        flips = (const int*)  d_in[0];
    }
    float* out = (float*)d_out;

    SignStickyPhaseReconstructor_kernel<<<B, 1024>>>(edc, flips, out);
}